// round 1
// baseline (speedup 1.0000x reference)
#include <cuda_runtime.h>

// TP_nonlinearity: B=512, MUL=64, dims {0:1, 1:3, 2:5}
// out0: [512,12288,1]  blocks: (0,0)@0, (1,1)@4096, (2,2)@8192
// out1: [512,16384,3]  blocks: (0,1)@0, (1,1)@4096, (1,2)@8192, (2,2)@12288
// out2: [512,16384,5]  blocks: (0,2)@0, (1,1)@4096, (1,2)@8192, (2,2)@12288
//
// Factored: z[t][m][M][j] = sum_n w_t[m,n,M] * x_{l2(t)}[b,j,n]   (stage 1, smem)
//           out_{l3}[b, off + i*64 + j, M] = sum_m x_{l1}[b,i,m] * z[t][m][M][j]

struct Params {
    const float* x0; const float* x1; const float* x2;
    const float* w[11];
    float* o0; float* o1; float* o2;
};

// triple order: (0,0,0)(0,1,1)(0,2,2)(1,1,0)(1,1,1)(1,1,2)(1,2,1)(1,2,2)(2,2,0)(2,2,1)(2,2,2)
__constant__ int c_zbase[12] = {0,1,4,9,12,21,36,45,60,65,80,105};
__constant__ int c_d3[11]    = {1,3,5,1,3,5,3,5,1,3,5};
__constant__ int c_d2[11]    = {1,3,5,3,3,3,5,5,5,5,5};
__constant__ int c_l2[11]    = {0,1,2,1,1,1,2,2,2,2,2};

template<int D1, int D3>
__device__ __forceinline__ void load_z(float* zr, const float* zs, int zbase, int j) {
#pragma unroll
    for (int r = 0; r < D1 * D3; ++r) zr[r] = zs[(zbase + r) * 64 + j];
}

template<int D1, int D3>
__device__ __forceinline__ void emit(float* __restrict__ outp,
                                     const float* xv, const float* zr) {
#pragma unroll
    for (int Mi = 0; Mi < D3; ++Mi) {
        float acc = xv[0] * zr[Mi];
#pragma unroll
        for (int m = 1; m < D1; ++m)
            acc = fmaf(xv[m], zr[m * D3 + Mi], acc);
        __stcs(outp + Mi, acc);
    }
}

__global__ __launch_bounds__(256) void tp_kernel(Params P) {
    __shared__ float xs0[64];
    __shared__ float xs1[64 * 3];
    __shared__ float xs2[64 * 5];
    __shared__ float zs[105 * 64];
    __shared__ const float* ws[11];

    const int tid   = threadIdx.x;
    const int b     = blockIdx.x >> 1;
    const int ihalf = blockIdx.x & 1;

    if (tid < 11) ws[tid] = P.w[tid];
    for (int e = tid; e < 64;  e += 256) xs0[e] = P.x0[b * 64  + e];
    for (int e = tid; e < 192; e += 256) xs1[e] = P.x1[b * 192 + e];
    for (int e = tid; e < 320; e += 256) xs2[e] = P.x2[b * 320 + e];
    __syncthreads();

    const int j = tid & 63;
    const int g = tid >> 6;   // 0..3

    // ---- stage 1: z[r][j], r in [0,105), warp-uniform r per iteration ----
    for (int r = g; r < 105; r += 4) {
        int t = 0;
#pragma unroll
        for (int u = 1; u < 11; ++u) t += (r >= c_zbase[u]);
        const int loc = r - c_zbase[t];
        const int d3 = c_d3[t], d2 = c_d2[t], l2 = c_l2[t];
        const int m = loc / d3, M = loc - m * d3;
        const float* w  = ws[t] + (m * d2) * d3 + M;
        const float* xr = (l2 == 0 ? xs0 : (l2 == 1 ? xs1 : xs2)) + j * d2;
        float acc = 0.f;
        for (int n = 0; n < d2; ++n)
            acc = fmaf(w[n * d3], xr[n], acc);
        zs[r * 64 + j] = acc;
    }
    __syncthreads();

    // ---- stage 2: per-thread fixed j, loop over 8 i's per l1-group ----
    const size_t b0 = (size_t)b * 12288;
    const size_t b1 = (size_t)b * 16384;

    // l1 = 0: pairs (0,0)->out0@0, (0,1)->out1@0, (0,2)->out2@0
    {
        float z0[1]; load_z<1,1>(z0, zs, 0, j);
        float z1[3]; load_z<1,3>(z1, zs, 1, j);
        float z2[5]; load_z<1,5>(z2, zs, 4, j);
#pragma unroll
        for (int k = 0; k < 8; ++k) {
            const int i = ihalf * 32 + g + 4 * k;
            const float xv[1] = { xs0[i] };
            const int c = i * 64 + j;
            emit<1,1>(P.o0 + b0 + c,            xv, z0);
            emit<1,3>(P.o1 + (b1 + c) * 3,      xv, z1);
            emit<1,5>(P.o2 + (b1 + c) * 5,      xv, z2);
        }
    }
    // l1 = 1: pairs (1,1) -> out0@4096,out1@4096,out2@4096 ; (1,2) -> out1@8192,out2@8192
    {
        float z30[3];  load_z<3,1>(z30, zs,  9, j);
        float z41[9];  load_z<3,3>(z41, zs, 12, j);
        float z52[15]; load_z<3,5>(z52, zs, 21, j);
        float z61[9];  load_z<3,3>(z61, zs, 36, j);
        float z72[15]; load_z<3,5>(z72, zs, 45, j);
#pragma unroll
        for (int k = 0; k < 8; ++k) {
            const int i = ihalf * 32 + g + 4 * k;
            const float xv[3] = { xs1[i*3+0], xs1[i*3+1], xs1[i*3+2] };
            const int c = i * 64 + j;
            emit<3,1>(P.o0 + b0 + 4096 + c,          xv, z30);
            emit<3,3>(P.o1 + (b1 + 4096 + c) * 3,    xv, z41);
            emit<3,5>(P.o2 + (b1 + 4096 + c) * 5,    xv, z52);
            emit<3,3>(P.o1 + (b1 + 8192 + c) * 3,    xv, z61);
            emit<3,5>(P.o2 + (b1 + 8192 + c) * 5,    xv, z72);
        }
    }
    // l1 = 2: pair (2,2) -> out0@8192, out1@12288, out2@12288
    {
        float z80[5];  load_z<5,1>(z80, zs, 60, j);
        float z91[15]; load_z<5,3>(z91, zs, 65, j);
        float zA2[25]; load_z<5,5>(zA2, zs, 80, j);
#pragma unroll
        for (int k = 0; k < 8; ++k) {
            const int i = ihalf * 32 + g + 4 * k;
            const float xv[5] = { xs2[i*5+0], xs2[i*5+1], xs2[i*5+2], xs2[i*5+3], xs2[i*5+4] };
            const int c = i * 64 + j;
            emit<5,1>(P.o0 + b0 + 8192 + c,           xv, z80);
            emit<5,3>(P.o1 + (b1 + 12288 + c) * 3,    xv, z91);
            emit<5,5>(P.o2 + (b1 + 12288 + c) * 5,    xv, zA2);
        }
    }
}

extern "C" void kernel_launch(void* const* d_in, const int* in_sizes, int n_in,
                              void* d_out, int out_size) {
    Params P;
    P.x0 = (const float*)d_in[0];
    P.x1 = (const float*)d_in[1];
    P.x2 = (const float*)d_in[2];
    for (int t = 0; t < 11; ++t) P.w[t] = (const float*)d_in[3 + t];
    float* out = (float*)d_out;
    P.o0 = out;
    P.o1 = out + (size_t)512 * 12288;
    P.o2 = out + (size_t)512 * 12288 + (size_t)512 * 16384 * 3;
    tp_kernel<<<1024, 256>>>(P);
}

// round 2
// speedup vs baseline: 1.6423x; 1.6423x over previous
#include <cuda_runtime.h>

// TP_nonlinearity: B=512, MUL=64, dims {0:1, 1:3, 2:5}
// out0: [512,12288,1]  blocks: (0,0)@0, (1,1)@4096, (2,2)@8192
// out1: [512,16384,3]  blocks: (0,1)@0, (1,1)@4096, (1,2)@8192, (2,2)@12288
// out2: [512,16384,5]  blocks: (0,2)@0, (1,1)@4096, (1,2)@8192, (2,2)@12288
//
// Stage 1 (smem): z[r][j] = sum_n w_t[m,n,M] * x_{l2}[b,j,n],  r enumerates (t,m,M)
// Stage 2: out[b, off + i*64 + j, M] = sum_m x_{l1}[b,i,m] * z[...][j]
// Stores for d3 in {3,5} staged per-warp through smem -> packed STG.128.

struct Params {
    const float* x0; const float* x1; const float* x2;
    const float* w[11];
    float* o0; float* o1; float* o2;
};

// triple order: (0,0,0)(0,1,1)(0,2,2)(1,1,0)(1,1,1)(1,1,2)(1,2,1)(1,2,2)(2,2,0)(2,2,1)(2,2,2)
__constant__ int c_zbase[12] = {0,1,4,9,12,21,36,45,60,65,80,105};
__constant__ int c_d3[11]    = {1,3,5,1,3,5,3,5,1,3,5};
__constant__ int c_d2[11]    = {1,3,5,3,3,3,5,5,5,5,5};
__constant__ int c_l2[11]    = {0,1,2,1,1,1,2,2,2,2,2};

template<int D1, int D3>
__device__ __forceinline__ void load_z(float* zr, const float* zs, int zbase, int j) {
#pragma unroll
    for (int r = 0; r < D1 * D3; ++r) zr[r] = zs[(zbase + r) * 64 + j];
}

template<int D1, int D3>
__device__ __forceinline__ void comp(float* acc, const float* xv, const float* zr) {
#pragma unroll
    for (int M = 0; M < D3; ++M) {
        float a = xv[0] * zr[M];
#pragma unroll
        for (int m = 1; m < D1; ++m)
            a = fmaf(xv[m], zr[m * D3 + M], a);
        acc[M] = a;
    }
}

// Per-warp staged store: 32 lanes x D3 floats -> packed float4 STG.
// rowp must be 16B aligned (row base is a multiple of 128*D3 bytes).
template<int D3>
__device__ __forceinline__ void stage_store(float* __restrict__ rowp, const float* acc,
                                            float* wb, int lane) {
#pragma unroll
    for (int M = 0; M < D3; ++M) wb[lane * D3 + M] = acc[M];
    __syncwarp();
    constexpr int NF4 = 8 * D3;  // float4 count for 32*D3 floats
#pragma unroll
    for (int s0 = 0; s0 < NF4; s0 += 32) {
        const int s = s0 + lane;
        if (s < NF4) {
            float4 v = *reinterpret_cast<const float4*>(wb + 4 * s);
            __stcs(reinterpret_cast<float4*>(rowp) + s, v);
        }
    }
    __syncwarp();
}

__global__ __launch_bounds__(256) void tp_kernel(Params P) {
    __shared__ float xs[64 * 9];       // x0:[0,64) | x1:[64,256) j*3 | x2:[256,576) j*5
    __shared__ float zs[105 * 64];
    __shared__ float wbuf[8 * 160];    // 160 floats per warp
    __shared__ const float* ws[11];

    const int tid   = threadIdx.x;
    const int b     = blockIdx.x >> 1;
    const int ihalf = blockIdx.x & 1;

    if (tid < 11) ws[tid] = P.w[tid];
    for (int e = tid; e < 64;  e += 256) xs[e]       = P.x0[b * 64  + e];
    for (int e = tid; e < 192; e += 256) xs[64 + e]  = P.x1[b * 192 + e];
    for (int e = tid; e < 320; e += 256) xs[256 + e] = P.x2[b * 320 + e];
    __syncthreads();

    const int j    = tid & 63;
    const int g    = tid >> 6;        // 0..3
    const int lane = tid & 31;
    const int jh   = (tid >> 5) & 1;  // which 32-j half this warp covers
    float* wb = &wbuf[(tid >> 5) * 160];

    // ---- stage 1: z[r][j] ----
    for (int r = g; r < 105; r += 4) {
        int t = 0;
#pragma unroll
        for (int u = 1; u < 11; ++u) t += (r >= c_zbase[u]);
        const int loc = r - c_zbase[t];
        const int d3 = c_d3[t], d2 = c_d2[t], l2 = c_l2[t];
        const int m = loc / d3, M = loc - m * d3;
        const float* w  = ws[t] + (m * d2) * d3 + M;
        const float* xr = (l2 == 0 ? xs + j : (l2 == 1 ? xs + 64 + j * 3 : xs + 256 + j * 5));
        float acc = 0.f;
        for (int n = 0; n < d2; ++n)
            acc = fmaf(w[n * d3], xr[n], acc);
        zs[r * 64 + j] = acc;
    }
    __syncthreads();

    // ---- stage 2 ----
    const size_t b0 = (size_t)b * 12288;
    const size_t b1 = (size_t)b * 16384;
    const int i0 = ihalf * 32 + g;           // i = i0 + 4k
    const size_t rbase = (size_t)i0 * 64 + jh * 32;  // staged row base (channel index)

    // ===== G0: l1=0 : (0,0,0)d  (0,1,1)s3  (0,2,2)s5 =====
    {
        float z0[1];  load_z<1,1>(z0, zs, 0, j);
        float z1[3];  load_z<1,3>(z1, zs, 1, j);
        float z2[5];  load_z<1,5>(z2, zs, 4, j);
        float* pd = P.o0 + b0 + (size_t)i0 * 64 + j;
        float* p1 = P.o1 + (b1 + rbase) * 3;
        float* p2 = P.o2 + (b1 + rbase) * 5;
#pragma unroll
        for (int k = 0; k < 8; ++k) {
            const int i = i0 + 4 * k;
            const float xv[1] = { xs[i] };
            __stcs(pd, xv[0] * z0[0]);
            float a1[3]; comp<1,3>(a1, xv, z1); stage_store<3>(p1, a1, wb, lane);
            float a2[5]; comp<1,5>(a2, xv, z2); stage_store<5>(p2, a2, wb, lane);
            pd += 256; p1 += 256 * 3; p2 += 256 * 5;
        }
    }
    // ===== G1: (1,1,0)d  (1,1,1)s3  (1,1,2)s5 =====
    {
        float za[3];  load_z<3,1>(za, zs,  9, j);
        float zb[9];  load_z<3,3>(zb, zs, 12, j);
        float zc[15]; load_z<3,5>(zc, zs, 21, j);
        float* pd = P.o0 + b0 + 4096 + (size_t)i0 * 64 + j;
        float* p1 = P.o1 + (b1 + 4096 + rbase) * 3;
        float* p2 = P.o2 + (b1 + 4096 + rbase) * 5;
#pragma unroll
        for (int k = 0; k < 8; ++k) {
            const int i = i0 + 4 * k;
            const float xv[3] = { xs[64 + i*3], xs[64 + i*3 + 1], xs[64 + i*3 + 2] };
            float a0[1]; comp<3,1>(a0, xv, za); __stcs(pd, a0[0]);
            float a1[3]; comp<3,3>(a1, xv, zb); stage_store<3>(p1, a1, wb, lane);
            float a2[5]; comp<3,5>(a2, xv, zc); stage_store<5>(p2, a2, wb, lane);
            pd += 256; p1 += 256 * 3; p2 += 256 * 5;
        }
    }
    // ===== G2: (1,2,1)s3  (1,2,2)s5 =====
    {
        float zb[9];  load_z<3,3>(zb, zs, 36, j);
        float zc[15]; load_z<3,5>(zc, zs, 45, j);
        float* p1 = P.o1 + (b1 + 8192 + rbase) * 3;
        float* p2 = P.o2 + (b1 + 8192 + rbase) * 5;
#pragma unroll
        for (int k = 0; k < 8; ++k) {
            const int i = i0 + 4 * k;
            const float xv[3] = { xs[64 + i*3], xs[64 + i*3 + 1], xs[64 + i*3 + 2] };
            float a1[3]; comp<3,3>(a1, xv, zb); stage_store<3>(p1, a1, wb, lane);
            float a2[5]; comp<3,5>(a2, xv, zc); stage_store<5>(p2, a2, wb, lane);
            p1 += 256 * 3; p2 += 256 * 5;
        }
    }
    // ===== G3: (2,2,0)d  (2,2,1)s3 =====
    {
        float za[5];  load_z<5,1>(za, zs, 60, j);
        float zb[15]; load_z<5,3>(zb, zs, 65, j);
        float* pd = P.o0 + b0 + 8192 + (size_t)i0 * 64 + j;
        float* p1 = P.o1 + (b1 + 12288 + rbase) * 3;
#pragma unroll
        for (int k = 0; k < 8; ++k) {
            const int i = i0 + 4 * k;
            const float xv[5] = { xs[256 + i*5], xs[256 + i*5 + 1], xs[256 + i*5 + 2],
                                  xs[256 + i*5 + 3], xs[256 + i*5 + 4] };
            float a0[1]; comp<5,1>(a0, xv, za); __stcs(pd, a0[0]);
            float a1[3]; comp<5,3>(a1, xv, zb); stage_store<3>(p1, a1, wb, lane);
            pd += 256; p1 += 256 * 3;
        }
    }
    // ===== G4: (2,2,2)s5 =====
    {
        float zc[25]; load_z<5,5>(zc, zs, 80, j);
        float* p2 = P.o2 + (b1 + 12288 + rbase) * 5;
#pragma unroll
        for (int k = 0; k < 8; ++k) {
            const int i = i0 + 4 * k;
            const float xv[5] = { xs[256 + i*5], xs[256 + i*5 + 1], xs[256 + i*5 + 2],
                                  xs[256 + i*5 + 3], xs[256 + i*5 + 4] };
            float a2[5]; comp<5,5>(a2, xv, zc); stage_store<5>(p2, a2, wb, lane);
            p2 += 256 * 5;
        }
    }
}

extern "C" void kernel_launch(void* const* d_in, const int* in_sizes, int n_in,
                              void* d_out, int out_size) {
    Params P;
    P.x0 = (const float*)d_in[0];
    P.x1 = (const float*)d_in[1];
    P.x2 = (const float*)d_in[2];
    for (int t = 0; t < 11; ++t) P.w[t] = (const float*)d_in[3 + t];
    float* out = (float*)d_out;
    P.o0 = out;
    P.o1 = out + (size_t)512 * 12288;
    P.o2 = out + (size_t)512 * 12288 + (size_t)512 * 16384 * 3;
    tp_kernel<<<1024, 256>>>(P);
}

// round 3
// speedup vs baseline: 2.0265x; 1.2340x over previous
#include <cuda_runtime.h>

// TP_nonlinearity: B=512, MUL=64, dims {0:1, 1:3, 2:5}
// out0: [512,12288,1]  blocks: (0,0)@0, (1,1)@4096, (2,2)@8192
// out1: [512,16384,3]  blocks: (0,1)@0, (1,1)@4096, (1,2)@8192, (2,2)@12288
// out2: [512,16384,5]  blocks: (0,2)@0, (1,1)@4096, (1,2)@8192, (2,2)@12288
//
// Stage 1 (smem): z[ZB+m*d3+M][j] = sum_n w_t[m,n,M] * x_{l2}[b,j,n]
// Stage 2: each thread owns d3 float4 output slots per 16-row chunk; 4 chunks
//          cover the full 64 rows of batch b. z loaded once per slot, reused
//          across all 4 chunks. Stores are single STG.128, fully coalesced.

struct Params {
    const float* x0; const float* x1; const float* x2;
    const float* w[11];
    float* o0; float* o1; float* o2;
};

// ---------------- stage 1: z = w . x_{l2} ----------------
template<int D1, int D2, int D3, int ZB, int XO>
__device__ __forceinline__ void stage1(const float* __restrict__ w,
                                       float* __restrict__ zs,
                                       const float* __restrict__ xs, int tid) {
    constexpr int NT = D1 * D3 * 64;
#pragma unroll 1
    for (int task = tid; task < NT; task += 256) {
        const int j  = task & 63;
        const int mm = task >> 6;            // m*D3 + M
        const int m  = mm / D3;
        const int M  = mm - m * D3;
        const float* wp = w + m * D2 * D3 + M;
        const float* xr = xs + XO + j * D2;
        float acc = 0.f;
#pragma unroll
        for (int n = 0; n < D2; ++n)
            acc = fmaf(__ldg(wp + n * D3), xr[n], acc);
        zs[(ZB + mm) * 64 + j] = acc;
    }
}

// ---------------- stage 2: direct float4 output ----------------
// outp: element pointer to block base = tensor + (b*CH + OFF)*D3 (16B aligned).
// Chunk ci covers rows [ci*16, ci*16+16); chunk has 256*D3 float4 slots.
// Thread owns slots s = q*256 + tid, q in [0,D3).
template<int D1, int D3, int ZB, int XO>
__device__ __forceinline__ void proc(float* __restrict__ outp,
                                     const float* __restrict__ zs,
                                     const float* __restrict__ xs, int tid) {
    float4* __restrict__ o4 = reinterpret_cast<float4*>(outp);
#pragma unroll 1
    for (int q = 0; q < D3; ++q) {
        const int s  = q * 256 + tid;
        const int f  = 4 * s;                 // flat float within chunk
        const int ii = f / (64 * D3);         // row-in-chunk, const per slot
        const int rem0 = f - ii * 64 * D3;

        // z for the 4 components, loaded once, reused over 4 chunks
        float zr[4][D1];
#pragma unroll
        for (int c = 0; c < 4; ++c) {
            const int rem = rem0 + c;
            const int j = rem / D3;
            const int M = rem - j * D3;
#pragma unroll
            for (int m = 0; m < D1; ++m)
                zr[c][m] = zs[(ZB + m * D3 + M) * 64 + j];
        }

#pragma unroll
        for (int ci = 0; ci < 4; ++ci) {
            const int i = ci * 16 + ii;
            float xv[D1];
#pragma unroll
            for (int m = 0; m < D1; ++m)
                xv[m] = xs[XO + i * D1 + m];

            float4 v;
            {
                float a0 = xv[0] * zr[0][0];
                float a1 = xv[0] * zr[1][0];
                float a2 = xv[0] * zr[2][0];
                float a3 = xv[0] * zr[3][0];
#pragma unroll
                for (int m = 1; m < D1; ++m) {
                    a0 = fmaf(xv[m], zr[0][m], a0);
                    a1 = fmaf(xv[m], zr[1][m], a1);
                    a2 = fmaf(xv[m], zr[2][m], a2);
                    a3 = fmaf(xv[m], zr[3][m], a3);
                }
                v.x = a0; v.y = a1; v.z = a2; v.w = a3;
            }
            __stcs(o4 + ci * (256 * D3) + s, v);
        }
    }
}

__global__ __launch_bounds__(256) void tp_kernel(Params P) {
    __shared__ float xs[64 * 9];     // x0:[0,64) | x1:[64,256) | x2:[256,576)
    __shared__ float zs[105 * 64];

    const int tid = threadIdx.x;
    const int b   = blockIdx.x;

    for (int e = tid; e < 64;  e += 256) xs[e]       = P.x0[b * 64  + e];
    for (int e = tid; e < 192; e += 256) xs[64 + e]  = P.x1[b * 192 + e];
    for (int e = tid; e < 320; e += 256) xs[256 + e] = P.x2[b * 320 + e];
    __syncthreads();

    // stage 1: one template instantiation per triple (l1,l2,l3)
    stage1<1,1,1,  0,   0>(P.w[0],  zs, xs, tid);  // (0,0,0)
    stage1<1,3,3,  1,  64>(P.w[1],  zs, xs, tid);  // (0,1,1)  x_l2 = x1
    stage1<1,5,5,  4, 256>(P.w[2],  zs, xs, tid);  // (0,2,2)  x_l2 = x2
    stage1<3,3,1,  9,  64>(P.w[3],  zs, xs, tid);  // (1,1,0)
    stage1<3,3,3, 12,  64>(P.w[4],  zs, xs, tid);  // (1,1,1)
    stage1<3,3,5, 21,  64>(P.w[5],  zs, xs, tid);  // (1,1,2)
    stage1<3,5,3, 36, 256>(P.w[6],  zs, xs, tid);  // (1,2,1)
    stage1<3,5,5, 45, 256>(P.w[7],  zs, xs, tid);  // (1,2,2)
    stage1<5,5,1, 60, 256>(P.w[8],  zs, xs, tid);  // (2,2,0)
    stage1<5,5,3, 65, 256>(P.w[9],  zs, xs, tid);  // (2,2,1)
    stage1<5,5,5, 80, 256>(P.w[10], zs, xs, tid);  // (2,2,2)
    __syncthreads();

    // stage 2
    const size_t bo0 = (size_t)b * 12288;
    const size_t bo1 = (size_t)b * 16384;

    proc<1,1, 0,   0>(P.o0 + bo0,                   zs, xs, tid);  // (0,0,0)
    proc<1,3, 1,   0>(P.o1 + (bo1)         * 3,     zs, xs, tid);  // (0,1,1)
    proc<1,5, 4,   0>(P.o2 + (bo1)         * 5,     zs, xs, tid);  // (0,2,2)
    proc<3,1, 9,  64>(P.o0 + bo0 + 4096,            zs, xs, tid);  // (1,1,0)
    proc<3,3,12,  64>(P.o1 + (bo1 + 4096)  * 3,     zs, xs, tid);  // (1,1,1)
    proc<3,5,21,  64>(P.o2 + (bo1 + 4096)  * 5,     zs, xs, tid);  // (1,1,2)
    proc<3,3,36,  64>(P.o1 + (bo1 + 8192)  * 3,     zs, xs, tid);  // (1,2,1)
    proc<3,5,45,  64>(P.o2 + (bo1 + 8192)  * 5,     zs, xs, tid);  // (1,2,2)
    proc<5,1,60, 256>(P.o0 + bo0 + 8192,            zs, xs, tid);  // (2,2,0)
    proc<5,3,65, 256>(P.o1 + (bo1 + 12288) * 3,     zs, xs, tid);  // (2,2,1)
    proc<5,5,80, 256>(P.o2 + (bo1 + 12288) * 5,     zs, xs, tid);  // (2,2,2)
}

extern "C" void kernel_launch(void* const* d_in, const int* in_sizes, int n_in,
                              void* d_out, int out_size) {
    Params P;
    P.x0 = (const float*)d_in[0];
    P.x1 = (const float*)d_in[1];
    P.x2 = (const float*)d_in[2];
    for (int t = 0; t < 11; ++t) P.w[t] = (const float*)d_in[3 + t];
    float* out = (float*)d_out;
    P.o0 = out;
    P.o1 = out + (size_t)512 * 12288;
    P.o2 = out + (size_t)512 * 12288 + (size_t)512 * 16384 * 3;
    tp_kernel<<<512, 256>>>(P);
}

// round 4
// speedup vs baseline: 2.1402x; 1.0561x over previous
#include <cuda_runtime.h>

// TP_nonlinearity: B=512, MUL=64, dims {0:1, 1:3, 2:5}
// out0: [512,12288,1]  blocks: (0,0)@0, (1,1)@4096, (2,2)@8192
// out1: [512,16384,3]  blocks: (0,1)@0, (1,1)@4096, (1,2)@8192, (2,2)@12288
// out2: [512,16384,5]  blocks: (0,2)@0, (1,1)@4096, (1,2)@8192, (2,2)@12288
//
// Stage 1 (smem): z[ZB+m*d3+M][j] = sum_n w_t[m,n,M] * x_{l2}[b,j,n]
// Stage 2: each thread owns d3 float4 output slots per 16-row chunk.
// Grid = 1024: 2 CTAs per batch element, each emits 2 of the 4 chunks
// (stage 1 duplicated across the pair — it is cheap; store parallelism wins).

struct Params {
    const float* x0; const float* x1; const float* x2;
    const float* w[11];
    float* o0; float* o1; float* o2;
};

// ---------------- stage 1: z = w . x_{l2} ----------------
template<int D1, int D2, int D3, int ZB, int XO>
__device__ __forceinline__ void stage1(const float* __restrict__ w,
                                       float* __restrict__ zs,
                                       const float* __restrict__ xs, int tid) {
    constexpr int NT = D1 * D3 * 64;
#pragma unroll 1
    for (int task = tid; task < NT; task += 256) {
        const int j  = task & 63;
        const int mm = task >> 6;            // m*D3 + M
        const int m  = mm / D3;
        const int M  = mm - m * D3;
        const float* wp = w + m * D2 * D3 + M;
        const float* xr = xs + XO + j * D2;
        float acc = 0.f;
#pragma unroll
        for (int n = 0; n < D2; ++n)
            acc = fmaf(__ldg(wp + n * D3), xr[n], acc);
        zs[(ZB + mm) * 64 + j] = acc;
    }
}

// ---------------- stage 2: direct float4 output ----------------
// outp points at this CTA's half: tensor + (b*CH + OFF + ibase*64)*D3.
// Each 16-row chunk has 256*D3 float4 slots; thread owns slots q*256+tid.
template<int D1, int D3, int ZB, int XO>
__device__ __forceinline__ void proc(float* __restrict__ outp,
                                     const float* __restrict__ zs,
                                     const float* __restrict__ xs,
                                     int tid, int ibase) {
    float4* __restrict__ o4 = reinterpret_cast<float4*>(outp);
#pragma unroll 1
    for (int q = 0; q < D3; ++q) {
        const int s  = q * 256 + tid;
        const int f  = 4 * s;                 // flat float within chunk
        const int ii = f / (64 * D3);         // row-in-chunk, const per slot
        const int rem0 = f - ii * 64 * D3;

        // z for the 4 components, loaded once, reused over both chunks
        float zr[4][D1];
#pragma unroll
        for (int c = 0; c < 4; ++c) {
            const int rem = rem0 + c;
            const int j = rem / D3;
            const int M = rem - j * D3;
#pragma unroll
            for (int m = 0; m < D1; ++m)
                zr[c][m] = zs[(ZB + m * D3 + M) * 64 + j];
        }

#pragma unroll
        for (int ci = 0; ci < 2; ++ci) {
            const int i = ibase + ci * 16 + ii;
            float xv[D1];
#pragma unroll
            for (int m = 0; m < D1; ++m)
                xv[m] = xs[XO + i * D1 + m];

            float4 v;
            {
                float a0 = xv[0] * zr[0][0];
                float a1 = xv[0] * zr[1][0];
                float a2 = xv[0] * zr[2][0];
                float a3 = xv[0] * zr[3][0];
#pragma unroll
                for (int m = 1; m < D1; ++m) {
                    a0 = fmaf(xv[m], zr[0][m], a0);
                    a1 = fmaf(xv[m], zr[1][m], a1);
                    a2 = fmaf(xv[m], zr[2][m], a2);
                    a3 = fmaf(xv[m], zr[3][m], a3);
                }
                v.x = a0; v.y = a1; v.z = a2; v.w = a3;
            }
            __stcs(o4 + ci * (256 * D3) + s, v);
        }
    }
}

__global__ __launch_bounds__(256) void tp_kernel(Params P) {
    __shared__ float xs[64 * 9];     // x0:[0,64) | x1:[64,256) | x2:[256,576)
    __shared__ float zs[105 * 64];

    const int tid   = threadIdx.x;
    const int b     = blockIdx.x >> 1;
    const int ibase = (blockIdx.x & 1) * 32;

    for (int e = tid; e < 64;  e += 256) xs[e]       = P.x0[b * 64  + e];
    for (int e = tid; e < 192; e += 256) xs[64 + e]  = P.x1[b * 192 + e];
    for (int e = tid; e < 320; e += 256) xs[256 + e] = P.x2[b * 320 + e];
    __syncthreads();

    // stage 1: one template instantiation per triple (l1,l2,l3)
    stage1<1,1,1,  0,   0>(P.w[0],  zs, xs, tid);  // (0,0,0)
    stage1<1,3,3,  1,  64>(P.w[1],  zs, xs, tid);  // (0,1,1)
    stage1<1,5,5,  4, 256>(P.w[2],  zs, xs, tid);  // (0,2,2)
    stage1<3,3,1,  9,  64>(P.w[3],  zs, xs, tid);  // (1,1,0)
    stage1<3,3,3, 12,  64>(P.w[4],  zs, xs, tid);  // (1,1,1)
    stage1<3,3,5, 21,  64>(P.w[5],  zs, xs, tid);  // (1,1,2)
    stage1<3,5,3, 36, 256>(P.w[6],  zs, xs, tid);  // (1,2,1)
    stage1<3,5,5, 45, 256>(P.w[7],  zs, xs, tid);  // (1,2,2)
    stage1<5,5,1, 60, 256>(P.w[8],  zs, xs, tid);  // (2,2,0)
    stage1<5,5,3, 65, 256>(P.w[9],  zs, xs, tid);  // (2,2,1)
    stage1<5,5,5, 80, 256>(P.w[10], zs, xs, tid);  // (2,2,2)
    __syncthreads();

    // stage 2 — pointers pre-offset to this CTA's 32-row half
    const size_t bo0 = (size_t)b * 12288 + (size_t)ibase * 64;
    const size_t bo1 = (size_t)b * 16384 + (size_t)ibase * 64;

    proc<1,1, 0,   0>(P.o0 + bo0,                 zs, xs, tid, ibase);  // (0,0,0)
    proc<1,3, 1,   0>(P.o1 + (bo1)         * 3,   zs, xs, tid, ibase);  // (0,1,1)
    proc<1,5, 4,   0>(P.o2 + (bo1)         * 5,   zs, xs, tid, ibase);  // (0,2,2)
    proc<3,1, 9,  64>(P.o0 + bo0 + 4096,          zs, xs, tid, ibase);  // (1,1,0)
    proc<3,3,12,  64>(P.o1 + (bo1 + 4096)  * 3,   zs, xs, tid, ibase);  // (1,1,1)
    proc<3,5,21,  64>(P.o2 + (bo1 + 4096)  * 5,   zs, xs, tid, ibase);  // (1,1,2)
    proc<3,3,36,  64>(P.o1 + (bo1 + 8192)  * 3,   zs, xs, tid, ibase);  // (1,2,1)
    proc<3,5,45,  64>(P.o2 + (bo1 + 8192)  * 5,   zs, xs, tid, ibase);  // (1,2,2)
    proc<5,1,60, 256>(P.o0 + bo0 + 8192,          zs, xs, tid, ibase);  // (2,2,0)
    proc<5,3,65, 256>(P.o1 + (bo1 + 12288) * 3,   zs, xs, tid, ibase);  // (2,2,1)
    proc<5,5,80, 256>(P.o2 + (bo1 + 12288) * 5,   zs, xs, tid, ibase);  // (2,2,2)
}

extern "C" void kernel_launch(void* const* d_in, const int* in_sizes, int n_in,
                              void* d_out, int out_size) {
    Params P;
    P.x0 = (const float*)d_in[0];
    P.x1 = (const float*)d_in[1];
    P.x2 = (const float*)d_in[2];
    for (int t = 0; t < 11; ++t) P.w[t] = (const float*)d_in[3 + t];
    float* out = (float*)d_out;
    P.o0 = out;
    P.o1 = out + (size_t)512 * 12288;
    P.o2 = out + (size_t)512 * 12288 + (size_t)512 * 16384 * 3;
    tp_kernel<<<1024, 256>>>(P);
}

// round 5
// speedup vs baseline: 2.2943x; 1.0720x over previous
#include <cuda_runtime.h>

// TP_nonlinearity: B=512, MUL=64, dims {0:1, 1:3, 2:5}
// out0: [512,12288,1]  blocks: (0,0)@0, (1,1)@4096, (2,2)@8192
// out1: [512,16384,3]  blocks: (0,1)@0, (1,1)@4096, (1,2)@8192, (2,2)@12288
// out2: [512,16384,5]  blocks: (0,2)@0, (1,1)@4096, (1,2)@8192, (2,2)@12288
//
// Stage 1: zc4[ZB4 + m*16*D3 + w] = float4 over c of
//          sum_n w_t[m,n,M(4w+c)] * x_{l2}[b, j(4w+c), n]   (slot-major layout)
// Stage 2: slot s = q*256+tid; w = s mod 16*D3; ii = s / (16*D3);
//          v = sum_m xv[m] * zc4[m][w]  (componentwise)  -> one STG.128.
// Grid 1024: 2 CTAs per batch element, each emits 2 of the 4 16-row chunks.

struct Params {
    const float* x0; const float* x1; const float* x2;
    const float* w[11];
    float* o0; float* o1; float* o2;
};

// ---------------- stage 1: slot-major z ----------------
template<int D1, int D2, int D3, int ZB4, int XO>
__device__ __forceinline__ void stage1(const float* __restrict__ w,
                                       float4* __restrict__ zc4,
                                       const float* __restrict__ xs, int tid) {
    constexpr int NT = D1 * 16 * D3;
#pragma unroll 1
    for (int task = tid; task < NT; task += 256) {
        const int m  = task / (16 * D3);
        const int ww = task - m * (16 * D3);
        const float* wrow = w + m * D2 * D3;
        float out[4];
#pragma unroll
        for (int c = 0; c < 4; ++c) {
            const int rem = 4 * ww + c;
            const int j = rem / D3;
            const int M = rem - j * D3;
            const float* xr = xs + XO + j * D2;
            float acc = 0.f;
#pragma unroll
            for (int n = 0; n < D2; ++n)
                acc = fmaf(__ldg(wrow + n * D3 + M), xr[n], acc);
            out[c] = acc;
        }
        float4 v; v.x = out[0]; v.y = out[1]; v.z = out[2]; v.w = out[3];
        zc4[ZB4 + m * (16 * D3) + ww] = v;
    }
}

// ---------------- stage 2: vectorized z, direct float4 output ----------------
template<int D1, int D3, int ZB4, int XO>
__device__ __forceinline__ void proc(float* __restrict__ outp,
                                     const float4* __restrict__ zc4,
                                     const float* __restrict__ xs,
                                     int tid, int ibase) {
    float4* __restrict__ o4 = reinterpret_cast<float4*>(outp);
#pragma unroll
    for (int q = 0; q < D3; ++q) {
        const int s  = q * 256 + tid;
        const int ii = s / (16 * D3);
        const int w  = s - ii * (16 * D3);

        float4 zm[D1];
#pragma unroll
        for (int m = 0; m < D1; ++m)
            zm[m] = zc4[ZB4 + m * (16 * D3) + w];

#pragma unroll
        for (int ci = 0; ci < 2; ++ci) {
            const int i = ibase + ci * 16 + ii;
            const float x0v = xs[XO + i * D1];
            float4 v;
            v.x = x0v * zm[0].x;
            v.y = x0v * zm[0].y;
            v.z = x0v * zm[0].z;
            v.w = x0v * zm[0].w;
#pragma unroll
            for (int m = 1; m < D1; ++m) {
                const float xv = xs[XO + i * D1 + m];
                v.x = fmaf(xv, zm[m].x, v.x);
                v.y = fmaf(xv, zm[m].y, v.y);
                v.z = fmaf(xv, zm[m].z, v.z);
                v.w = fmaf(xv, zm[m].w, v.w);
            }
            __stcs(o4 + ci * (256 * D3) + s, v);
        }
    }
}

__global__ __launch_bounds__(256) void tp_kernel(Params P) {
    __shared__ float  xs[64 * 9];     // x0:[0,64) | x1:[64,256) | x2:[256,576)
    __shared__ float4 zc4[1680];      // slot-major z, 26.9 KB

    const int tid   = threadIdx.x;
    const int b     = blockIdx.x >> 1;
    const int ibase = (blockIdx.x & 1) * 32;

    for (int e = tid; e < 64;  e += 256) xs[e]       = P.x0[b * 64  + e];
    for (int e = tid; e < 192; e += 256) xs[64 + e]  = P.x1[b * 192 + e];
    for (int e = tid; e < 320; e += 256) xs[256 + e] = P.x2[b * 320 + e];
    __syncthreads();

    // stage 1: one instantiation per triple (l1,l2,l3); XO = x_{l2} offset
    stage1<1,1,1,    0,   0>(P.w[0],  zc4, xs, tid);  // (0,0,0)
    stage1<1,3,3,   16,  64>(P.w[1],  zc4, xs, tid);  // (0,1,1)
    stage1<1,5,5,   64, 256>(P.w[2],  zc4, xs, tid);  // (0,2,2)
    stage1<3,3,1,  144,  64>(P.w[3],  zc4, xs, tid);  // (1,1,0)
    stage1<3,3,3,  192,  64>(P.w[4],  zc4, xs, tid);  // (1,1,1)
    stage1<3,3,5,  336,  64>(P.w[5],  zc4, xs, tid);  // (1,1,2)
    stage1<3,5,3,  576, 256>(P.w[6],  zc4, xs, tid);  // (1,2,1)
    stage1<3,5,5,  720, 256>(P.w[7],  zc4, xs, tid);  // (1,2,2)
    stage1<5,5,1,  960, 256>(P.w[8],  zc4, xs, tid);  // (2,2,0)
    stage1<5,5,3, 1040, 256>(P.w[9],  zc4, xs, tid);  // (2,2,1)
    stage1<5,5,5, 1280, 256>(P.w[10], zc4, xs, tid);  // (2,2,2)
    __syncthreads();

    // stage 2 — pointers pre-offset to this CTA's 32-row half; XO = x_{l1}
    const size_t bo0 = (size_t)b * 12288 + (size_t)ibase * 64;
    const size_t bo1 = (size_t)b * 16384 + (size_t)ibase * 64;

    proc<1,1,    0,   0>(P.o0 + bo0,                 zc4, xs, tid, ibase);  // (0,0,0)
    proc<1,3,   16,   0>(P.o1 + (bo1)         * 3,   zc4, xs, tid, ibase);  // (0,1,1)
    proc<1,5,   64,   0>(P.o2 + (bo1)         * 5,   zc4, xs, tid, ibase);  // (0,2,2)
    proc<3,1,  144,  64>(P.o0 + bo0 + 4096,          zc4, xs, tid, ibase);  // (1,1,0)
    proc<3,3,  192,  64>(P.o1 + (bo1 + 4096)  * 3,   zc4, xs, tid, ibase);  // (1,1,1)
    proc<3,5,  336,  64>(P.o2 + (bo1 + 4096)  * 5,   zc4, xs, tid, ibase);  // (1,1,2)
    proc<3,3,  576,  64>(P.o1 + (bo1 + 8192)  * 3,   zc4, xs, tid, ibase);  // (1,2,1)
    proc<3,5,  720,  64>(P.o2 + (bo1 + 8192)  * 5,   zc4, xs, tid, ibase);  // (1,2,2)
    proc<5,1,  960, 256>(P.o0 + bo0 + 8192,          zc4, xs, tid, ibase);  // (2,2,0)
    proc<5,3, 1040, 256>(P.o1 + (bo1 + 12288) * 3,   zc4, xs, tid, ibase);  // (2,2,1)
    proc<5,5, 1280, 256>(P.o2 + (bo1 + 12288) * 5,   zc4, xs, tid, ibase);  // (2,2,2)
}

extern "C" void kernel_launch(void* const* d_in, const int* in_sizes, int n_in,
                              void* d_out, int out_size) {
    Params P;
    P.x0 = (const float*)d_in[0];
    P.x1 = (const float*)d_in[1];
    P.x2 = (const float*)d_in[2];
    for (int t = 0; t < 11; ++t) P.w[t] = (const float*)d_in[3 + t];
    float* out = (float*)d_out;
    P.o0 = out;
    P.o1 = out + (size_t)512 * 12288;
    P.o2 = out + (size_t)512 * 12288 + (size_t)512 * 16384 * 3;
    tp_kernel<<<1024, 256>>>(P);
}

// round 6
// speedup vs baseline: 2.3608x; 1.0290x over previous
#include <cuda_runtime.h>

// TP_nonlinearity: B=512, MUL=64, dims {0:1, 1:3, 2:5}
// out0: [512,12288,1]  blocks: (0,0)@0, (1,1)@4096, (2,2)@8192
// out1: [512,16384,3]  blocks: (0,1)@0, (1,1)@4096, (1,2)@8192, (2,2)@12288
// out2: [512,16384,5]  blocks: (0,2)@0, (1,1)@4096, (1,2)@8192, (2,2)@12288
//
// Stage 1: zc4[ZB4 + m*16*D3 + w] = float4 over c of
//          sum_n w_t[m,n,M(4w+c)] * x_{l2}[b, j(4w+c), n]   (slot-major layout)
// Stage 2: slot s = q*256+tid; w = s mod 16*D3; ii = s / (16*D3);
//          v = sum_m xv[m] * zc4[m][w]  (componentwise)  -> one STG.128.
// Grid 1024: 2 CTAs per batch element, each emits 2 of the 4 16-row chunks.
// launch_bounds(256,5) + unroll-1 slot loop: keep regs ~50 for 5 CTAs/SM.

struct Params {
    const float* x0; const float* x1; const float* x2;
    const float* w[11];
    float* o0; float* o1; float* o2;
};

// ---------------- stage 1: slot-major z ----------------
template<int D1, int D2, int D3, int ZB4, int XO>
__device__ __forceinline__ void stage1(const float* __restrict__ w,
                                       float4* __restrict__ zc4,
                                       const float* __restrict__ xs, int tid) {
    constexpr int NT = D1 * 16 * D3;
#pragma unroll 1
    for (int task = tid; task < NT; task += 256) {
        const int m  = task / (16 * D3);
        const int ww = task - m * (16 * D3);
        const float* wrow = w + m * D2 * D3;
        float out[4];
#pragma unroll
        for (int c = 0; c < 4; ++c) {
            const int rem = 4 * ww + c;
            const int j = rem / D3;
            const int M = rem - j * D3;
            const float* xr = xs + XO + j * D2;
            float acc = 0.f;
#pragma unroll
            for (int n = 0; n < D2; ++n)
                acc = fmaf(__ldg(wrow + n * D3 + M), xr[n], acc);
            out[c] = acc;
        }
        float4 v; v.x = out[0]; v.y = out[1]; v.z = out[2]; v.w = out[3];
        zc4[ZB4 + m * (16 * D3) + ww] = v;
    }
}

// ---------------- stage 2: vectorized z, direct float4 output ----------------
template<int D1, int D3, int ZB4, int XO>
__device__ __forceinline__ void proc(float* __restrict__ outp,
                                     const float4* __restrict__ zc4,
                                     const float* __restrict__ xs,
                                     int tid, int ibase) {
    float4* __restrict__ o4 = reinterpret_cast<float4*>(outp);
#pragma unroll 1
    for (int q = 0; q < D3; ++q) {
        const int s  = q * 256 + tid;
        const int ii = s / (16 * D3);
        const int w  = s - ii * (16 * D3);

        float4 zm[D1];
#pragma unroll
        for (int m = 0; m < D1; ++m)
            zm[m] = zc4[ZB4 + m * (16 * D3) + w];

#pragma unroll
        for (int ci = 0; ci < 2; ++ci) {
            const int i = ibase + ci * 16 + ii;
            const float x0v = xs[XO + i * D1];
            float4 v;
            v.x = x0v * zm[0].x;
            v.y = x0v * zm[0].y;
            v.z = x0v * zm[0].z;
            v.w = x0v * zm[0].w;
#pragma unroll
            for (int m = 1; m < D1; ++m) {
                const float xv = xs[XO + i * D1 + m];
                v.x = fmaf(xv, zm[m].x, v.x);
                v.y = fmaf(xv, zm[m].y, v.y);
                v.z = fmaf(xv, zm[m].z, v.z);
                v.w = fmaf(xv, zm[m].w, v.w);
            }
            __stcs(o4 + ci * (256 * D3) + s, v);
        }
    }
}

__global__ __launch_bounds__(256, 5) void tp_kernel(Params P) {
    __shared__ float  xs[64 * 9];     // x0:[0,64) | x1:[64,256) | x2:[256,576)
    __shared__ float4 zc4[1680];      // slot-major z, 26.9 KB

    const int tid   = threadIdx.x;
    const int b     = blockIdx.x >> 1;
    const int ibase = (blockIdx.x & 1) * 32;

    for (int e = tid; e < 64;  e += 256) xs[e]       = P.x0[b * 64  + e];
    for (int e = tid; e < 192; e += 256) xs[64 + e]  = P.x1[b * 192 + e];
    for (int e = tid; e < 320; e += 256) xs[256 + e] = P.x2[b * 320 + e];
    __syncthreads();

    // stage 1: one instantiation per triple (l1,l2,l3); XO = x_{l2} offset
    stage1<1,1,1,    0,   0>(P.w[0],  zc4, xs, tid);  // (0,0,0)
    stage1<1,3,3,   16,  64>(P.w[1],  zc4, xs, tid);  // (0,1,1)
    stage1<1,5,5,   64, 256>(P.w[2],  zc4, xs, tid);  // (0,2,2)
    stage1<3,3,1,  144,  64>(P.w[3],  zc4, xs, tid);  // (1,1,0)
    stage1<3,3,3,  192,  64>(P.w[4],  zc4, xs, tid);  // (1,1,1)
    stage1<3,3,5,  336,  64>(P.w[5],  zc4, xs, tid);  // (1,1,2)
    stage1<3,5,3,  576, 256>(P.w[6],  zc4, xs, tid);  // (1,2,1)
    stage1<3,5,5,  720, 256>(P.w[7],  zc4, xs, tid);  // (1,2,2)
    stage1<5,5,1,  960, 256>(P.w[8],  zc4, xs, tid);  // (2,2,0)
    stage1<5,5,3, 1040, 256>(P.w[9],  zc4, xs, tid);  // (2,2,1)
    stage1<5,5,5, 1280, 256>(P.w[10], zc4, xs, tid);  // (2,2,2)
    __syncthreads();

    // stage 2 — pointers pre-offset to this CTA's 32-row half; XO = x_{l1}
    const size_t bo0 = (size_t)b * 12288 + (size_t)ibase * 64;
    const size_t bo1 = (size_t)b * 16384 + (size_t)ibase * 64;

    proc<1,1,    0,   0>(P.o0 + bo0,                 zc4, xs, tid, ibase);  // (0,0,0)
    proc<1,3,   16,   0>(P.o1 + (bo1)         * 3,   zc4, xs, tid, ibase);  // (0,1,1)
    proc<1,5,   64,   0>(P.o2 + (bo1)         * 5,   zc4, xs, tid, ibase);  // (0,2,2)
    proc<3,1,  144,  64>(P.o0 + bo0 + 4096,          zc4, xs, tid, ibase);  // (1,1,0)
    proc<3,3,  192,  64>(P.o1 + (bo1 + 4096)  * 3,   zc4, xs, tid, ibase);  // (1,1,1)
    proc<3,5,  336,  64>(P.o2 + (bo1 + 4096)  * 5,   zc4, xs, tid, ibase);  // (1,1,2)
    proc<3,3,  576,  64>(P.o1 + (bo1 + 8192)  * 3,   zc4, xs, tid, ibase);  // (1,2,1)
    proc<3,5,  720,  64>(P.o2 + (bo1 + 8192)  * 5,   zc4, xs, tid, ibase);  // (1,2,2)
    proc<5,1,  960, 256>(P.o0 + bo0 + 8192,          zc4, xs, tid, ibase);  // (2,2,0)
    proc<5,3, 1040, 256>(P.o1 + (bo1 + 12288) * 3,   zc4, xs, tid, ibase);  // (2,2,1)
    proc<5,5, 1280, 256>(P.o2 + (bo1 + 12288) * 5,   zc4, xs, tid, ibase);  // (2,2,2)
}

extern "C" void kernel_launch(void* const* d_in, const int* in_sizes, int n_in,
                              void* d_out, int out_size) {
    Params P;
    P.x0 = (const float*)d_in[0];
    P.x1 = (const float*)d_in[1];
    P.x2 = (const float*)d_in[2];
    for (int t = 0; t < 11; ++t) P.w[t] = (const float*)d_in[3 + t];
    float* out = (float*)d_out;
    P.o0 = out;
    P.o1 = out + (size_t)512 * 12288;
    P.o2 = out + (size_t)512 * 12288 + (size_t)512 * 16384 * 3;
    tp_kernel<<<1024, 256>>>(P);
}